// round 5
// baseline (speedup 1.0000x reference)
#include <cuda_runtime.h>
#include <stdint.h>

#define NB     32
#define CIN    256
#define HDIM   56
#define HW     3136
#define PIXI   100352          // 32*56*56 interior pixels
#define OC     256
#define HP     58
#define IMGP   (HP*HP)         // 3364
#define NPAD   (NB*IMGP)       // 107648 padded pixels = 841*128
#define GUARD  64
#define XROWS  (NPAD + 2*GUARD)
#define KTOT   2304            // 9 taps * 256 ch
#define NCHUNK 18              // K chunks of 128 bytes
#define MT     128
#define NTILES (NPAD/MT)       // 841
#define A_BYTES 16384          // 128 rows * 128B
#define B_BYTES 16384          // 128 oc  * 128B
#define STAGE_BYTES (A_BYTES + B_BYTES)
#define STAGES 3
#define EPI_STRIDE 132         // floats, bank-conflict-free epilogue
#define SMEM_DYN  ((STAGES*STAGE_BYTES > 128*EPI_STRIDE*4) ? STAGES*STAGE_BYTES : 128*EPI_STRIDE*4)

// ---- device scratch ----
__device__ float g_alpha[NB];
__device__ float g_m[OC];
__device__ float g_part[NB*16];
__device__ __align__(256) signed char g_xs[(size_t)XROWS*256]; // padded signs ±1, pad 0
__device__ __align__(256) signed char g_ws[(size_t)OC*KTOT];   // weight signs [o][tap*256+c]

// ===================== helpers =====================
__device__ __forceinline__ uint32_t smem_u32(const void* p) {
    uint32_t a;
    asm("{ .reg .u64 t; cvta.to.shared.u64 t, %1; cvt.u32.u64 %0, t; }" : "=r"(a) : "l"(p));
    return a;
}
__device__ __forceinline__ unsigned sw128(unsigned o) { return o ^ ((o >> 3) & 0x70); }
__device__ __forceinline__ void cpa16(uint32_t dst, const void* src) {
    asm volatile("cp.async.cg.shared.global [%0], [%1], 16;" :: "r"(dst), "l"(src));
}
__device__ __forceinline__ void cpa_commit() {
    asm volatile("cp.async.commit_group;" ::: "memory");
}
__device__ __forceinline__ void cpa_wait2() {
    asm volatile("cp.async.wait_group 2;" ::: "memory");
}
__device__ __forceinline__ void ldsm4(uint32_t (&r)[4], uint32_t addr) {
    asm volatile("ldmatrix.sync.aligned.m8n8.x4.shared.b16 {%0,%1,%2,%3}, [%4];"
                 : "=r"(r[0]), "=r"(r[1]), "=r"(r[2]), "=r"(r[3]) : "r"(addr));
}
__device__ __forceinline__ void imma(int* c, const uint32_t* a, uint32_t b0, uint32_t b1) {
    asm volatile("mma.sync.aligned.m16n8k32.row.col.s32.s8.s8.s32 "
                 "{%0,%1,%2,%3}, {%4,%5,%6,%7}, {%8,%9}, {%0,%1,%2,%3};"
                 : "+r"(c[0]), "+r"(c[1]), "+r"(c[2]), "+r"(c[3])
                 : "r"(a[0]), "r"(a[1]), "r"(a[2]), "r"(a[3]), "r"(b0), "r"(b1));
}

// ===================== prep kernels =====================
__global__ void k_absmean_x(const float* __restrict__ x) {
    int n = blockIdx.x >> 4;
    int chunk = blockIdx.x & 15;
    const float4* xv = (const float4*)x + (size_t)n * 200704 + (size_t)chunk * 12544;
    float s = 0.f;
    for (int i = threadIdx.x; i < 12544; i += 256) {
        float4 v = xv[i];
        s += fabsf(v.x) + fabsf(v.y) + fabsf(v.z) + fabsf(v.w);
    }
    __shared__ float sh[8];
    #pragma unroll
    for (int d = 16; d > 0; d >>= 1) s += __shfl_down_sync(0xffffffffu, s, d);
    if ((threadIdx.x & 31) == 0) sh[threadIdx.x >> 5] = s;
    __syncthreads();
    if (threadIdx.x == 0) {
        float t = 0.f;
        #pragma unroll
        for (int i = 0; i < 8; i++) t += sh[i];
        g_part[blockIdx.x] = t;
    }
}
__global__ void k_alpha() {
    int n = threadIdx.x;
    float s = 0.f;
    #pragma unroll
    for (int i = 0; i < 16; i++) s += g_part[n * 16 + i];
    float a = 2.f * s / (float)(CIN * HW);
    g_alpha[n] = fmaxf(a, 1e-5f);
}
__global__ void k_prep_w(const float* __restrict__ wt) {
    int o = blockIdx.x, c = threadIdx.x;
    const float* wo = wt + (size_t)o * KTOT + (size_t)c * 9;
    float v[9];
    float s = 0.f;
    #pragma unroll
    for (int t = 0; t < 9; t++) { v[t] = wo[t]; s += fabsf(v[t]); }
    __shared__ float sh[8];
    #pragma unroll
    for (int d = 16; d > 0; d >>= 1) s += __shfl_down_sync(0xffffffffu, s, d);
    if ((threadIdx.x & 31) == 0) sh[threadIdx.x >> 5] = s;
    __syncthreads();
    if (threadIdx.x == 0) {
        float t = 0.f;
        #pragma unroll
        for (int i = 0; i < 8; i++) t += sh[i];
        g_m[o] = t / (float)KTOT;
    }
    #pragma unroll
    for (int t = 0; t < 9; t++)
        g_ws[(size_t)o * KTOT + t * 256 + c] = (v[t] > 0.f) ? 1 : -1;
}
__global__ void k_prep_x(const float* __restrict__ x) {
    int p = blockIdx.x * 256 + threadIdx.x;
    int cg = blockIdx.y;
    int n = p / HW, hw = p - n * HW;
    int h = hw / HDIM, w = hw - h * HDIM;
    const float* xp = x + ((size_t)(n * CIN + cg * 32)) * HW + hw;
    unsigned b[8];
    #pragma unroll
    for (int q = 0; q < 8; q++) {
        unsigned word = 0;
        #pragma unroll
        for (int j = 0; j < 4; j++) {
            float v = xp[(size_t)(q * 4 + j) * HW];
            word |= (v > 0.f ? 0x01u : 0xFFu) << (j * 8);
        }
        b[q] = word;
    }
    size_t row = (size_t)n * IMGP + (size_t)(h + 1) * HP + (w + 1) + GUARD;
    uint4* dst = (uint4*)(g_xs + row * 256 + cg * 32);
    dst[0] = make_uint4(b[0], b[1], b[2], b[3]);
    dst[1] = make_uint4(b[4], b[5], b[6], b[7]);
}
__global__ void k_zero_border() {
    int i = blockIdx.x * 256 + threadIdx.x;
    int rowi = i >> 4, seg = i & 15;
    size_t row;
    if (rowi < 2 * GUARD) {
        row = (rowi < GUARD) ? (size_t)rowi : (size_t)(GUARD + NPAD + (rowi - GUARD));
    } else {
        int idx = rowi - 2 * GUARD;
        int n = idx / 228, j = idx - n * 228;
        int hp, wp;
        if (j < 58)       { hp = 0;  wp = j; }
        else if (j < 116) { hp = 57; wp = j - 58; }
        else if (j < 172) { wp = 0;  hp = j - 116 + 1; }
        else              { wp = 57; hp = j - 172 + 1; }
        row = (size_t)GUARD + (size_t)n * IMGP + hp * HP + wp;
    }
    ((uint4*)(g_xs + row * 256))[seg] = make_uint4(0, 0, 0, 0);
}

// ===================== int8 implicit-GEMM conv =====================
__global__ void __launch_bounds__(256, 2) k_gemm(float* __restrict__ out) {
    extern __shared__ char smem[];
    const uint32_t sb = smem_u32(smem);
    __shared__ float sm_m[128];

    const int tid = threadIdx.x;
    const int wid = tid >> 5;
    const int lane = tid & 31;
    const int warp_m = wid & 3;          // 0..3 -> M rows 32*warp_m
    const int warp_n = wid >> 2;         // 0..1 -> N cols 64*warp_n

    const int j0  = blockIdx.x * MT;
    const int ob0 = blockIdx.y * 128;

    // per-lane ldmatrix address pieces
    const int r16   = (lane & 7) + ((lane >> 3) & 1) * 8;   // row within 16-block
    const int mask  = (lane & 7) * 16;                       // swizzle XOR mask
    const int khoff = ((lane >> 4) & 1) * 16;                // matrices 2,3: k+16
    const int a_r0  = warp_m * 32 + r16;
    const int b_rb  = warp_n * 64 + r16;

    int acc[2][8][4];
    #pragma unroll
    for (int m = 0; m < 2; m++)
        #pragma unroll
        for (int g = 0; g < 8; g++)
            #pragma unroll
            for (int k = 0; k < 4; k++) acc[m][g][k] = 0;

    // chunk loader: 2048 x cp.async(16B) over 256 threads
    auto load_chunk = [&](int q) {
        int tap = q >> 1, c0 = (q & 1) << 7;
        int dh = tap / 3 - 1, dw = tap % 3 - 1;
        long grow = (long)j0 + GUARD + dh * HP + dw;
        uint32_t base = sb + (q % STAGES) * STAGE_BYTES;
        #pragma unroll
        for (int it = 0; it < 8; it++) {
            int i = tid + it * 256;
            if (i < 1024) {                              // A
                int r = i >> 3, seg = i & 7;
                const void* src = g_xs + ((size_t)(grow + r)) * 256 + c0 + seg * 16;
                cpa16(base + sw128((unsigned)(r * 128 + seg * 16)), src);
            } else {                                     // B
                int ib = i - 1024;
                int o = ib >> 3, seg = ib & 7;
                const void* src = g_ws + (size_t)(ob0 + o) * KTOT + tap * 256 + c0 + seg * 16;
                cpa16(base + A_BYTES + sw128((unsigned)(o * 128 + seg * 16)), src);
            }
        }
    };

    if (tid < 128) sm_m[tid] = g_m[ob0 + tid];

    load_chunk(0); cpa_commit();
    load_chunk(1); cpa_commit();
    load_chunk(2); cpa_commit();

    for (int q = 0; q < NCHUNK; q++) {
        cpa_wait2();
        __syncthreads();
        uint32_t sA = sb + (q % STAGES) * STAGE_BYTES;
        uint32_t sB = sA + A_BYTES;
        #pragma unroll
        for (int ks = 0; ks < 4; ks++) {
            int kx = (ks * 32 + khoff) ^ mask;
            uint32_t af[2][4];
            ldsm4(af[0], sA + (unsigned)(a_r0 * 128) + kx);
            ldsm4(af[1], sA + (unsigned)((a_r0 + 16) * 128) + kx);
            #pragma unroll
            for (int gg = 0; gg < 4; gg++) {             // each x4 covers 2 n-groups
                uint32_t bf[4];
                ldsm4(bf, sB + (unsigned)((b_rb + gg * 16) * 128) + kx);
                imma(acc[0][gg * 2 + 0], af[0], bf[0], bf[2]);
                imma(acc[1][gg * 2 + 0], af[1], bf[0], bf[2]);
                imma(acc[0][gg * 2 + 1], af[0], bf[1], bf[3]);
                imma(acc[1][gg * 2 + 1], af[1], bf[1], bf[3]);
            }
        }
        __syncthreads();
        if (q + 3 < NCHUNK) load_chunk(q + 3);
        cpa_commit();
    }

    // -------- epilogue: transpose through smem, coalesced stores --------
    __syncthreads();
    float* sf = (float*)smem;                            // [128 oc][EPI_STRIDE]
    #pragma unroll
    for (int m = 0; m < 2; m++) {
        int row = warp_m * 32 + m * 16 + (lane >> 2);
        #pragma unroll
        for (int g = 0; g < 8; g++) {
            int col = warp_n * 64 + g * 8 + (lane & 3) * 2;
            sf[(col    ) * EPI_STRIDE + row    ] = (float)acc[m][g][0];
            sf[(col + 1) * EPI_STRIDE + row    ] = (float)acc[m][g][1];
            sf[(col    ) * EPI_STRIDE + row + 8] = (float)acc[m][g][2];
            sf[(col + 1) * EPI_STRIDE + row + 8] = (float)acc[m][g][3];
        }
    }
    __syncthreads();

    int p_local = tid & 127, half = tid >> 7;
    int j = j0 + p_local;
    int n = j / IMGP, rem = j - n * IMGP;
    int hp = rem / HP, wp = rem - hp * HP;
    bool inter = (hp >= 1 && hp <= 56 && wp >= 1 && wp <= 56);
    float av = g_alpha[n];
    float* ob = out + ((size_t)n * OC + ob0) * HW + (hp - 1) * HDIM + (wp - 1);
    #pragma unroll 4
    for (int oo = 0; oo < 64; oo++) {
        int ol = half * 64 + oo;
        float v = sf[ol * EPI_STRIDE + p_local] * av * sm_m[ol];
        if (inter) ob[(size_t)ol * HW] = v;
    }
}

// ===================== launch =====================
extern "C" void kernel_launch(void* const* d_in, const int* in_sizes, int n_in,
                              void* d_out, int out_size) {
    const float* x  = (const float*)d_in[0];
    const float* wt = (const float*)d_in[1];
    float* out = (float*)d_out;

    k_absmean_x<<<NB * 16, 256>>>(x);
    k_alpha<<<1, 32>>>();
    k_prep_w<<<OC, 256>>>(wt);
    k_prep_x<<<dim3(PIXI / 256, 8), 256>>>(x);
    k_zero_border<<<464, 256>>>();

    static int smem_set = 0;
    if (!smem_set) {
        cudaFuncSetAttribute(k_gemm, cudaFuncAttributeMaxDynamicSharedMemorySize, SMEM_DYN);
        smem_set = 1;
    }
    k_gemm<<<dim3(NTILES, 2), 256, SMEM_DYN>>>(out);
}